// round 1
// baseline (speedup 1.0000x reference)
#include <cuda_runtime.h>

#define WIDTH  512
#define HEIGHT 512
#define ROWS   32          // output rows per block
#define TPB    128         // threads/block; each thread owns 4 x positions -> full 512-wide row

// Gaussian 3-tap weights for sigma=1.5, normalized (2*W0 + W1 == 1 exactly in fp32)
#define W0f 0.30780133f
#define W1f 0.38439734f
#define C1f 1.0e-4f
#define C2f 9.0e-4f

__device__ double g_acc;

__global__ void k_init() { g_acc = 0.0; }

__device__ __forceinline__ float hs(float l, float c, float r) {
    // 3-tap horizontal Gaussian: W0*(l+r) + W1*c
    return fmaf(W1f, c, W0f * (l + r));
}

__global__ __launch_bounds__(TPB)
void k_ssim(const float* __restrict__ A, const float* __restrict__ B) {
    const int plane = blockIdx.y;
    const int y0    = blockIdx.x * ROWS;
    const float* a = A + plane * (WIDTH * HEIGHT);
    const float* b = B + plane * (WIDTH * HEIGHT);

    const int t    = threadIdx.x;
    const int lane = t & 31;
    const int x0   = t << 2;

    // streaming vertical partials: P1 = needs one more row, P2 = needs two more.
    // layout [quantity(5)][px(4)] flattened
    float P1[20], P2[20];
#pragma unroll
    for (int i = 0; i < 20; ++i) { P1[i] = 0.f; P2[i] = 0.f; }

    float acc = 0.f;

#pragma unroll 1
    for (int it = 0; it < ROWS + 2; ++it) {
        const int r = y0 - 1 + it;
        const bool rv = (r >= 0) && (r < HEIGHT);

        float4 av, bv;
        if (rv) {
            av = *reinterpret_cast<const float4*>(a + r * WIDTH + x0);
            bv = *reinterpret_cast<const float4*>(b + r * WIDTH + x0);
        } else {
            av = make_float4(0.f, 0.f, 0.f, 0.f);
            bv = make_float4(0.f, 0.f, 0.f, 0.f);
        }

        // halo via intra-warp shuffle; warp-edge lanes fall back to a scalar load
        float la = __shfl_up_sync(0xffffffffu, av.w, 1);
        float ra = __shfl_down_sync(0xffffffffu, av.x, 1);
        float lb = __shfl_up_sync(0xffffffffu, bv.w, 1);
        float rb = __shfl_down_sync(0xffffffffu, bv.x, 1);
        if (lane == 0) {
            la = (rv && x0 > 0) ? a[r * WIDTH + x0 - 1] : 0.f;
            lb = (rv && x0 > 0) ? b[r * WIDTH + x0 - 1] : 0.f;
        }
        if (lane == 31) {
            ra = (rv && x0 + 4 < WIDTH) ? a[r * WIDTH + x0 + 4] : 0.f;
            rb = (rv && x0 + 4 < WIDTH) ? b[r * WIDTH + x0 + 4] : 0.f;
        }

        float va[6] = { la, av.x, av.y, av.z, av.w, ra };
        float vb[6] = { lb, bv.x, bv.y, bv.z, bv.w, rb };
        float paa[6], pbb[6], pab[6];
#pragma unroll
        for (int j = 0; j < 6; ++j) {
            paa[j] = va[j] * va[j];
            pbb[j] = vb[j] * vb[j];
            pab[j] = va[j] * vb[j];
        }

        // horizontal 3-tap sums for the 5 quantities, 4 output columns each
        float h0[4], h1[4], h2[4], h3[4], h4[4];
#pragma unroll
        for (int i = 0; i < 4; ++i) {
            h0[i] = hs(va[i],  va[i + 1],  va[i + 2]);
            h1[i] = hs(vb[i],  vb[i + 1],  vb[i + 2]);
            h2[i] = hs(paa[i], paa[i + 1], paa[i + 2]);
            h3[i] = hs(pbb[i], pbb[i + 1], pbb[i + 2]);
            h4[i] = hs(pab[i], pab[i + 1], pab[i + 2]);
        }

        const bool emit = (it >= 2);   // output row r-1 in [y0, y0+ROWS)
#pragma unroll
        for (int i = 0; i < 4; ++i) {
            if (emit) {
                float mu1 = fmaf(W0f, h0[i], P1[0 * 4 + i]);
                float mu2 = fmaf(W0f, h1[i], P1[1 * 4 + i]);
                float s11 = fmaf(W0f, h2[i], P1[2 * 4 + i]);
                float s22 = fmaf(W0f, h3[i], P1[3 * 4 + i]);
                float s12 = fmaf(W0f, h4[i], P1[4 * 4 + i]);

                float m11 = mu1 * mu1;
                float m22 = mu2 * mu2;
                float m12 = mu1 * mu2;

                float n1 = fmaf(2.f, m12, C1f);
                float n2 = fmaf(2.f, s12 - m12, C2f);
                float d1 = (m11 + m22) + C1f;
                float d2 = ((s11 - m11) + (s22 - m22)) + C2f;

                acc += __fdividef(n1 * n2, d1 * d2);
            }
            P1[0 * 4 + i] = fmaf(W1f, h0[i], P2[0 * 4 + i]);  P2[0 * 4 + i] = W0f * h0[i];
            P1[1 * 4 + i] = fmaf(W1f, h1[i], P2[1 * 4 + i]);  P2[1 * 4 + i] = W0f * h1[i];
            P1[2 * 4 + i] = fmaf(W1f, h2[i], P2[2 * 4 + i]);  P2[2 * 4 + i] = W0f * h2[i];
            P1[3 * 4 + i] = fmaf(W1f, h3[i], P2[3 * 4 + i]);  P2[3 * 4 + i] = W0f * h3[i];
            P1[4 * 4 + i] = fmaf(W1f, h4[i], P2[4 * 4 + i]);  P2[4 * 4 + i] = W0f * h4[i];
        }
    }

    // block reduction
    __shared__ float red[TPB];
    red[t] = acc;
    __syncthreads();
#pragma unroll
    for (int s = TPB / 2; s > 0; s >>= 1) {
        if (t < s) red[t] += red[t + s];
        __syncthreads();
    }
    if (t == 0) atomicAdd(&g_acc, (double)red[0]);
}

__global__ void k_fin(float* out) {
    out[0] = (float)(1.0 - g_acc);
}

extern "C" void kernel_launch(void* const* d_in, const int* in_sizes, int n_in,
                              void* d_out, int out_size) {
    const float* A = (const float*)d_in[0];
    const float* B = (const float*)d_in[1];
    float* out = (float*)d_out;

    const int planes = in_sizes[0] / (WIDTH * HEIGHT);   // 32*3 = 96

    k_init<<<1, 1>>>();
    dim3 grid(HEIGHT / ROWS, planes);
    k_ssim<<<grid, TPB>>>(A, B);
    k_fin<<<1, 1>>>(out);
}